// round 3
// baseline (speedup 1.0000x reference)
#include <cuda_runtime.h>
#include <math.h>

#define NROWS 65536
#define IN_DIM 1024
#define H1D 512
#define H2D 256
#define LATD 64
#define NCODE 1024
#define COMMIT_BETA 0.25

// -------- scratch (device globals: allocation-free per harness rules) --------
__device__ float g_h1[(size_t)NROWS * H1D];   // 134 MB  (h1, then d2)
__device__ float g_h2[(size_t)NROWS * H2D];   // 67 MB   (h2, then d1)
__device__ float g_zq[(size_t)NROWS * LATD];  // 17 MB
__device__ float g_esq[NCODE];
__device__ double g_loss;

// packed dual fp32 FMA: each lane is IEEE rn fp32 -> bitwise == two fmaf calls
__device__ __forceinline__ void ffma2(unsigned long long& c,
                                      unsigned long long a,
                                      unsigned long long b)
{
    asm("fma.rn.f32x2 %0, %1, %2, %0;" : "+l"(c) : "l"(a), "l"(b));
}

// ============================================================================
// Double-buffered SGEMM with packed f32x2 FMAs.
// C = act(A[M,K] @ B[K,N] + bias), row-major fp32. ACT: 0=none,1=relu,2=tanh
// A-tile stored DUPLICATED in smem (each value twice) so (a,a) pairs load as
// vectors; B-tile pairs are naturally contiguous. Accumulation order over k
// is unchanged -> bitwise identical to the scalar version.
// ============================================================================
template<int BM,int BN,int BK,int TM,int TN,int ACT>
__global__ __launch_bounds__((BM/TM)*(BN/TN), 2)
void gemm_bias_act(const float* __restrict__ A, const float* __restrict__ B,
                   const float* __restrict__ bias, float* __restrict__ C,
                   int M, int N, int K)
{
    constexpr int NT = (BM/TM)*(BN/TN);
    constexpr int LA = (BM*BK)/(NT*4);
    constexpr int LB = (BK*BN)/(NT*4);
    constexpr int TP = TN/2;          // packed accumulator columns

    __shared__ __align__(16) float As[2][BK][2*BM];   // duplicated A values
    __shared__ __align__(16) float Bs[2][BK][BN];

    const int tid = threadIdx.x;
    const int m0 = blockIdx.x * BM;
    const int n0 = blockIdx.y * BN;
    const int tx = tid % (BN/TN);
    const int ty = tid / (BN/TN);

    unsigned long long acc2[TM][TP];
    #pragma unroll
    for (int i = 0; i < TM; i++)
        #pragma unroll
        for (int p = 0; p < TP; p++) acc2[i][p] = 0ull;

    float4 ra[LA], rb[LB];

    // ---- prologue: load tile 0 into buffer 0 ----
    #pragma unroll
    for (int j = 0; j < LA; j++) {
        int i = (tid + j*NT) * 4;
        int r = i / BK, c = i % BK;
        ra[j] = *reinterpret_cast<const float4*>(&A[(size_t)(m0 + r)*K + c]);
    }
    #pragma unroll
    for (int j = 0; j < LB; j++) {
        int i = (tid + j*NT) * 4;
        int r = i / BN, c = i % BN;
        rb[j] = *reinterpret_cast<const float4*>(&B[(size_t)r*N + n0 + c]);
    }
    #pragma unroll
    for (int j = 0; j < LA; j++) {
        int i = (tid + j*NT) * 4;
        int r = i / BK, c = i % BK;
        *reinterpret_cast<float2*>(&As[0][c+0][2*r]) = make_float2(ra[j].x, ra[j].x);
        *reinterpret_cast<float2*>(&As[0][c+1][2*r]) = make_float2(ra[j].y, ra[j].y);
        *reinterpret_cast<float2*>(&As[0][c+2][2*r]) = make_float2(ra[j].z, ra[j].z);
        *reinterpret_cast<float2*>(&As[0][c+3][2*r]) = make_float2(ra[j].w, ra[j].w);
    }
    #pragma unroll
    for (int j = 0; j < LB; j++) {
        int i = (tid + j*NT) * 4;
        int r = i / BN, c = i % BN;
        *reinterpret_cast<float4*>(&Bs[0][r][c]) = rb[j];
    }
    __syncthreads();

    const int ntiles = K / BK;
    #pragma unroll 1
    for (int t = 1; t < ntiles; t++) {
        const int k0 = t * BK;
        // prefetch next tile into registers
        #pragma unroll
        for (int j = 0; j < LA; j++) {
            int i = (tid + j*NT) * 4;
            int r = i / BK, c = i % BK;
            ra[j] = *reinterpret_cast<const float4*>(&A[(size_t)(m0 + r)*K + k0 + c]);
        }
        #pragma unroll
        for (int j = 0; j < LB; j++) {
            int i = (tid + j*NT) * 4;
            int r = i / BN, c = i % BN;
            rb[j] = *reinterpret_cast<const float4*>(&B[(size_t)(k0 + r)*N + n0 + c]);
        }
        // compute on current buffer
        const int cur = (t - 1) & 1;
        #pragma unroll
        for (int k = 0; k < BK; k++) {
            unsigned long long aa[TM], bb[TP];
            const ulonglong2* ap =
                reinterpret_cast<const ulonglong2*>(&As[cur][k][2*ty*TM]);
            #pragma unroll
            for (int i = 0; i < TM/2; i++) {
                ulonglong2 v = ap[i]; aa[2*i] = v.x; aa[2*i+1] = v.y;
            }
            const ulonglong2* bp =
                reinterpret_cast<const ulonglong2*>(&Bs[cur][k][tx*TN]);
            #pragma unroll
            for (int j = 0; j < TP/2; j++) {
                ulonglong2 v = bp[j]; bb[2*j] = v.x; bb[2*j+1] = v.y;
            }
            #pragma unroll
            for (int i = 0; i < TM; i++)
                #pragma unroll
                for (int p = 0; p < TP; p++)
                    ffma2(acc2[i][p], aa[i], bb[p]);
        }
        // store prefetched tile into next buffer
        const int nxt = t & 1;
        #pragma unroll
        for (int j = 0; j < LA; j++) {
            int i = (tid + j*NT) * 4;
            int r = i / BK, c = i % BK;
            *reinterpret_cast<float2*>(&As[nxt][c+0][2*r]) = make_float2(ra[j].x, ra[j].x);
            *reinterpret_cast<float2*>(&As[nxt][c+1][2*r]) = make_float2(ra[j].y, ra[j].y);
            *reinterpret_cast<float2*>(&As[nxt][c+2][2*r]) = make_float2(ra[j].z, ra[j].z);
            *reinterpret_cast<float2*>(&As[nxt][c+3][2*r]) = make_float2(ra[j].w, ra[j].w);
        }
        #pragma unroll
        for (int j = 0; j < LB; j++) {
            int i = (tid + j*NT) * 4;
            int r = i / BN, c = i % BN;
            *reinterpret_cast<float4*>(&Bs[nxt][r][c]) = rb[j];
        }
        __syncthreads();
    }
    // last tile
    {
        const int cur = (ntiles - 1) & 1;
        #pragma unroll
        for (int k = 0; k < BK; k++) {
            unsigned long long aa[TM], bb[TP];
            const ulonglong2* ap =
                reinterpret_cast<const ulonglong2*>(&As[cur][k][2*ty*TM]);
            #pragma unroll
            for (int i = 0; i < TM/2; i++) {
                ulonglong2 v = ap[i]; aa[2*i] = v.x; aa[2*i+1] = v.y;
            }
            const ulonglong2* bp =
                reinterpret_cast<const ulonglong2*>(&Bs[cur][k][tx*TN]);
            #pragma unroll
            for (int j = 0; j < TP/2; j++) {
                ulonglong2 v = bp[j]; bb[2*j] = v.x; bb[2*j+1] = v.y;
            }
            #pragma unroll
            for (int i = 0; i < TM; i++)
                #pragma unroll
                for (int p = 0; p < TP; p++)
                    ffma2(acc2[i][p], aa[i], bb[p]);
        }
    }

    // ---- epilogue: bias + activation, vectorized stores ----
    float bv[TN];
    #pragma unroll
    for (int j = 0; j < TN; j++) bv[j] = bias[n0 + tx*TN + j];
    #pragma unroll
    for (int i = 0; i < TM; i++) {
        const int row = m0 + ty*TM + i;
        float* Cp = &C[(size_t)row*N + n0 + tx*TN];
        float cvals[TN];
        #pragma unroll
        for (int p = 0; p < TP; p++) {
            float2 f = *reinterpret_cast<float2*>(&acc2[i][p]);
            cvals[2*p]   = f.x;
            cvals[2*p+1] = f.y;
        }
        #pragma unroll
        for (int j = 0; j < TN; j += 4) {
            float vv[4];
            #pragma unroll
            for (int q = 0; q < 4; q++) {
                float u = cvals[j+q] + bv[j+q];
                if (ACT == 1) u = fmaxf(u, 0.f);
                else if (ACT == 2) u = tanhf(u);
                vv[q] = u;
            }
            *reinterpret_cast<float4*>(&Cp[j]) = make_float4(vv[0], vv[1], vv[2], vv[3]);
        }
    }
}

// ============================================================================
// prep: codebook squared norms + zero the loss accumulator (runs every launch)
// sequential-order fp32 FMA to mirror the reference reduction rounding.
// ============================================================================
__global__ void prep_kernel(const float* __restrict__ cb)
{
    const int c = blockIdx.x * blockDim.x + threadIdx.x;
    if (c == 0) g_loss = 0.0;
    if (c < NCODE) {
        const float* p = &cb[(size_t)c * LATD];
        float s = 0.f;
        #pragma unroll
        for (int i = 0; i < LATD; i++) s = fmaf(p[i], p[i], s);
        g_esq[c] = s;
    }
}

// ============================================================================
// VQ: per-row argmin over 1024 codes (dim 64), gather z_q, commitment loss.
// Replicates reference fp32 rounding of dists = (z_sq - 2*(z.e)) + e_sq so
// near-tie rows resolve identically (strict < ascending == argmin first-min).
// UNCHANGED from the passing round (bitwise-critical).
// ============================================================================
__global__ __launch_bounds__(256)
void vq_kernel(const float* __restrict__ z, const float* __restrict__ cb,
               float* __restrict__ zq, float* __restrict__ idx_out)
{
    __shared__ __align__(16) float4 sc[128 * 16];   // 128 codes x 64 f32 = 32KB
    __shared__ float sesq[128];
    __shared__ float wsum[8];

    const int tid = threadIdx.x;
    const int row = blockIdx.x * 256 + tid;

    float4 zr[16];
    const float4* zp = reinterpret_cast<const float4*>(&z[(size_t)row * LATD]);
    #pragma unroll
    for (int i = 0; i < 16; i++) zr[i] = zp[i];

    // z_sq: sequential in-order fp32 FMA (matches reference reduction)
    float z_sq = 0.f;
    #pragma unroll
    for (int i = 0; i < 16; i++) {
        z_sq = fmaf(zr[i].x, zr[i].x, z_sq);
        z_sq = fmaf(zr[i].y, zr[i].y, z_sq);
        z_sq = fmaf(zr[i].z, zr[i].z, z_sq);
        z_sq = fmaf(zr[i].w, zr[i].w, z_sq);
    }

    float best = 3.4028235e38f;
    int bi = 0;
    for (int c0 = 0; c0 < NCODE; c0 += 128) {
        __syncthreads();
        const float4* cp = reinterpret_cast<const float4*>(&cb[(size_t)c0 * LATD]);
        #pragma unroll
        for (int j = 0; j < 8; j++) sc[tid + j*256] = cp[tid + j*256];
        if (tid < 128) sesq[tid] = g_esq[c0 + tid];
        __syncthreads();

        #pragma unroll 4
        for (int c = 0; c < 128; c++) {
            const float4* e = &sc[c * 16];
            float acc = 0.f;
            #pragma unroll
            for (int i = 0; i < 16; i++) {
                float4 v = e[i];
                acc = fmaf(zr[i].x, v.x, acc);
                acc = fmaf(zr[i].y, v.y, acc);
                acc = fmaf(zr[i].z, v.z, acc);
                acc = fmaf(zr[i].w, v.w, acc);
            }
            // reference association: (z_sq - 2*zc) + e_sq, all fp32 rounded
            float t = z_sq - 2.0f * acc;
            float d = t + sesq[c];
            if (d < best) { best = d; bi = c0 + c; }
        }
    }

    // gather z_q + per-row commitment sum
    const float4* ep = reinterpret_cast<const float4*>(&cb[(size_t)bi * LATD]);
    float4* qp = reinterpret_cast<float4*>(&zq[(size_t)row * LATD]);
    float ls = 0.f;
    #pragma unroll
    for (int i = 0; i < 16; i++) {
        float4 e = ep[i];
        qp[i] = e;
        float dx = e.x - zr[i].x, dy = e.y - zr[i].y;
        float dz = e.z - zr[i].z, dw = e.w - zr[i].w;
        ls += dx*dx + dy*dy + dz*dz + dw*dw;
    }
    idx_out[row] = (float)bi;

    // block reduction of loss -> double atomic (numerically stable)
    #pragma unroll
    for (int o = 16; o > 0; o >>= 1) ls += __shfl_down_sync(0xffffffffu, ls, o);
    if ((tid & 31) == 0) wsum[tid >> 5] = ls;
    __syncthreads();
    if (tid == 0) {
        float s = 0.f;
        #pragma unroll
        for (int i = 0; i < 8; i++) s += wsum[i];
        atomicAdd(&g_loss, (double)s);
    }
}

__global__ void fin_kernel(float* __restrict__ loss_out)
{
    loss_out[0] = (float)(COMMIT_BETA * g_loss / ((double)NROWS * LATD));
}

// ============================================================================
// launch
// ============================================================================
extern "C" void kernel_launch(void* const* d_in, const int* in_sizes, int n_in,
                              void* d_out, int out_size)
{
    const float* x   = (const float*)d_in[0];
    const float* We1 = (const float*)d_in[1];
    const float* be1 = (const float*)d_in[2];
    const float* We2 = (const float*)d_in[3];
    const float* be2 = (const float*)d_in[4];
    const float* We3 = (const float*)d_in[5];
    const float* be3 = (const float*)d_in[6];
    const float* cb  = (const float*)d_in[7];
    const float* Wd1 = (const float*)d_in[8];
    const float* bd1 = (const float*)d_in[9];
    const float* Wd2 = (const float*)d_in[10];
    const float* bd2 = (const float*)d_in[11];
    const float* Wd3 = (const float*)d_in[12];
    const float* bd3 = (const float*)d_in[13];

    float* out   = (float*)d_out;
    float* xrec  = out;                                  // [N, 1024]
    float* zout  = out + (size_t)NROWS * IN_DIM;         // [N, 64]
    float* idxo  = zout + (size_t)NROWS * LATD;          // [N]
    float* losso = idxo + NROWS;                         // [1]

    float *h1, *h2, *zq;
    cudaGetSymbolAddress((void**)&h1, g_h1);
    cudaGetSymbolAddress((void**)&h2, g_h2);
    cudaGetSymbolAddress((void**)&zq, g_zq);

    prep_kernel<<<4, 256>>>(cb);

    // encoder
    gemm_bias_act<128,128,8,8,8,1><<<dim3(NROWS/128, 4), 256>>>(x,  We1, be1, h1,   NROWS, 512,  1024);
    gemm_bias_act<128,128,8,8,8,1><<<dim3(NROWS/128, 2), 256>>>(h1, We2, be2, h2,   NROWS, 256,  512);
    gemm_bias_act<128, 64,16,8,4,0><<<dim3(NROWS/128, 1), 256>>>(h2, We3, be3, zout, NROWS, 64,   256);

    // vector quantization (reads z from d_out region)
    vq_kernel<<<NROWS/256, 256>>>(zout, cb, zq, idxo);

    // decoder (z_q_st forward value == z_q)
    gemm_bias_act<128,128,8,8,8,1><<<dim3(NROWS/128, 2), 256>>>(zq, Wd1, bd1, h2,   NROWS, 256,  64);
    gemm_bias_act<128,128,8,8,8,1><<<dim3(NROWS/128, 4), 256>>>(h2, Wd2, bd2, h1,   NROWS, 512,  256);
    gemm_bias_act<128,128,8,8,8,2><<<dim3(NROWS/128, 8), 256>>>(h1, Wd3, bd3, xrec, NROWS, 1024, 512);

    fin_kernel<<<1, 1>>>(losso);
}

// round 5
// speedup vs baseline: 1.5448x; 1.5448x over previous
#include <cuda_runtime.h>
#include <cuda_bf16.h>
#include <math.h>
#include <stdint.h>

#define NROWS 65536
#define IN_DIM 1024
#define H1D 512
#define H2D 256
#define LATD 64
#define NCODE 1024
#define COMMIT_BETA 0.25

// -------- scratch (device globals: allocation-free per harness rules) --------
__device__ float g_h1[(size_t)NROWS * H1D];   // 134 MB  (h1, then d2 out)
__device__ float g_h2[(size_t)NROWS * H2D];   // 67 MB   (h2, then d1 out)
__device__ float g_zq[(size_t)NROWS * LATD];  // 17 MB
__device__ float g_esq[NCODE];
__device__ double g_loss;
// split decoder weights, transposed to [N, K] bf16
__device__ __nv_bfloat16 g_w1h[H2D * LATD],   g_w1l[H2D * LATD];
__device__ __nv_bfloat16 g_w2h[H1D * H2D],    g_w2l[H1D * H2D];
__device__ __nv_bfloat16 g_w3h[IN_DIM * H1D], g_w3l[IN_DIM * H1D];

__device__ __forceinline__ uint32_t smem_u32(const void* p) {
    uint32_t a;
    asm("{ .reg .u64 t; cvta.to.shared.u64 t, %1; cvt.u32.u64 %0, t; }"
        : "=r"(a) : "l"(p));
    return a;
}
__device__ __forceinline__ void ldsm_x4(uint32_t& r0, uint32_t& r1,
                                        uint32_t& r2, uint32_t& r3, uint32_t addr) {
    asm volatile("ldmatrix.sync.aligned.m8n8.x4.shared.b16 {%0,%1,%2,%3}, [%4];"
                 : "=r"(r0), "=r"(r1), "=r"(r2), "=r"(r3) : "r"(addr));
}
__device__ __forceinline__ void mma_bf16(float* c, const uint32_t* a, const uint32_t* b) {
    asm volatile("mma.sync.aligned.m16n8k16.row.col.f32.bf16.bf16.f32 "
        "{%0,%1,%2,%3},{%4,%5,%6,%7},{%8,%9},{%0,%1,%2,%3};"
        : "+f"(c[0]), "+f"(c[1]), "+f"(c[2]), "+f"(c[3])
        : "r"(a[0]), "r"(a[1]), "r"(a[2]), "r"(a[3]), "r"(b[0]), "r"(b[1]));
}

// ============================================================================
// Decoder GEMM via warp-level bf16 MMA (legacy HMMA path; no 'a'-gated PTX).
// C = act(A[M,K]f32 @ W[K,N]f32 + bias), 2-term bf16 split:
//   C += Ah*Bh + Al*Bh + Ah*Bl  (fp32 accumulators)
// A split in-kernel; W pre-split + transposed ([N,K] bf16).
// CTA 128x128, BK=32, 8 warps (2x4 -> warp tile 64x32). ACT: 1=relu, 2=tanh
// grid = (N/128, M/128): consecutive CTAs share the A block in L2.
// ============================================================================
#define ASTR 40   // smem row stride in bf16 elems (80 B) -> conflict-free ldmatrix

template<int ACT>
__global__ __launch_bounds__(256, 1)
void mma_gemm(const float* __restrict__ A,
              const __nv_bfloat16* __restrict__ Wh,
              const __nv_bfloat16* __restrict__ Wl,
              const float* __restrict__ bias, float* __restrict__ C,
              int K, int N)
{
    __shared__ __align__(16) __nv_bfloat16 sAh[128 * ASTR];
    __shared__ __align__(16) __nv_bfloat16 sAl[128 * ASTR];
    __shared__ __align__(16) __nv_bfloat16 sBh[128 * ASTR];
    __shared__ __align__(16) __nv_bfloat16 sBl[128 * ASTR];

    const int tid = threadIdx.x;
    const int lane = tid & 31, wid = tid >> 5;
    const int m0 = blockIdx.y * 128, n0 = blockIdx.x * 128;
    const int wm = (wid & 1) * 64, wn = (wid >> 1) * 32;

    const uint32_t aAh = smem_u32(sAh), aAl = smem_u32(sAl);
    const uint32_t aBh = smem_u32(sBh), aBl = smem_u32(sBl);

    float acc[4][4][4];
    #pragma unroll
    for (int i = 0; i < 4; i++)
        #pragma unroll
        for (int j = 0; j < 4; j++)
            #pragma unroll
            for (int q = 0; q < 4; q++) acc[i][j][q] = 0.f;

    // per-thread staging map: 2 threads per row (128 rows)
    const int arow = tid >> 1;
    const int aq = tid & 1;

    float4 ra[4];
    uint4 rbh[2], rbl[2];

    auto loadG = [&](int k0) {
        const float4* ap = reinterpret_cast<const float4*>(
            &A[(size_t)(m0 + arow) * K + k0 + aq * 16]);
        #pragma unroll
        for (int j = 0; j < 4; j++) ra[j] = ap[j];
        const uint4* bph = reinterpret_cast<const uint4*>(
            &Wh[(size_t)(n0 + arow) * K + k0]);
        const uint4* bpl = reinterpret_cast<const uint4*>(
            &Wl[(size_t)(n0 + arow) * K + k0]);
        #pragma unroll
        for (int j = 0; j < 2; j++) {
            rbh[j] = bph[aq * 2 + j];
            rbl[j] = bpl[aq * 2 + j];
        }
    };
    auto storeS = [&]() {
        #pragma unroll
        for (int j = 0; j < 4; j++) {
            float4 v = ra[j];
            __nv_bfloat16 h0 = __float2bfloat16_rn(v.x);
            __nv_bfloat16 h1 = __float2bfloat16_rn(v.y);
            __nv_bfloat16 h2 = __float2bfloat16_rn(v.z);
            __nv_bfloat16 h3 = __float2bfloat16_rn(v.w);
            __nv_bfloat16 l0 = __float2bfloat16_rn(v.x - __bfloat162float(h0));
            __nv_bfloat16 l1 = __float2bfloat16_rn(v.y - __bfloat162float(h1));
            __nv_bfloat16 l2 = __float2bfloat16_rn(v.z - __bfloat162float(h2));
            __nv_bfloat16 l3 = __float2bfloat16_rn(v.w - __bfloat162float(h3));
            uint32_t hp0 = (uint32_t)__bfloat16_as_ushort(h0) |
                           ((uint32_t)__bfloat16_as_ushort(h1) << 16);
            uint32_t hp1 = (uint32_t)__bfloat16_as_ushort(h2) |
                           ((uint32_t)__bfloat16_as_ushort(h3) << 16);
            uint32_t lp0 = (uint32_t)__bfloat16_as_ushort(l0) |
                           ((uint32_t)__bfloat16_as_ushort(l1) << 16);
            uint32_t lp1 = (uint32_t)__bfloat16_as_ushort(l2) |
                           ((uint32_t)__bfloat16_as_ushort(l3) << 16);
            uint32_t off = (uint32_t)(arow * 80 + aq * 32 + j * 8);
            asm volatile("st.shared.v2.b32 [%0], {%1,%2};"
                         :: "r"(aAh + off), "r"(hp0), "r"(hp1) : "memory");
            asm volatile("st.shared.v2.b32 [%0], {%1,%2};"
                         :: "r"(aAl + off), "r"(lp0), "r"(lp1) : "memory");
        }
        #pragma unroll
        for (int j = 0; j < 2; j++) {
            uint32_t off = (uint32_t)(arow * 80 + (aq * 2 + j) * 16);
            asm volatile("st.shared.v4.b32 [%0], {%1,%2,%3,%4};"
                         :: "r"(aBh + off), "r"(rbh[j].x), "r"(rbh[j].y),
                            "r"(rbh[j].z), "r"(rbh[j].w) : "memory");
            asm volatile("st.shared.v4.b32 [%0], {%1,%2,%3,%4};"
                         :: "r"(aBl + off), "r"(rbl[j].x), "r"(rbl[j].y),
                            "r"(rbl[j].z), "r"(rbl[j].w) : "memory");
        }
    };
    auto compute = [&]() {
        #pragma unroll
        for (int ks = 0; ks < 2; ks++) {
            uint32_t ah[4][4], al[4][4], bh[4][2], bl[4][2];
            const int arl = lane & 15;
            const uint32_t ab = (uint32_t)((lane >> 4) * 16 + ks * 32);
            #pragma unroll
            for (int mt = 0; mt < 4; mt++) {
                uint32_t off = (uint32_t)((wm + mt * 16 + arl) * 80) + ab;
                ldsm_x4(ah[mt][0], ah[mt][1], ah[mt][2], ah[mt][3], aAh + off);
                ldsm_x4(al[mt][0], al[mt][1], al[mt][2], al[mt][3], aAl + off);
            }
            const int bn = (lane & 7) + ((lane >> 4) << 3);
            const uint32_t bb = (uint32_t)(((lane >> 3) & 1) * 16 + ks * 32);
            #pragma unroll
            for (int np = 0; np < 2; np++) {
                uint32_t off = (uint32_t)((wn + np * 16 + bn) * 80) + bb;
                uint32_t r0, r1, r2, r3;
                ldsm_x4(r0, r1, r2, r3, aBh + off);
                bh[np*2][0] = r0; bh[np*2][1] = r1;
                bh[np*2+1][0] = r2; bh[np*2+1][1] = r3;
                ldsm_x4(r0, r1, r2, r3, aBl + off);
                bl[np*2][0] = r0; bl[np*2][1] = r1;
                bl[np*2+1][0] = r2; bl[np*2+1][1] = r3;
            }
            #pragma unroll
            for (int mt = 0; mt < 4; mt++)
                #pragma unroll
                for (int nt = 0; nt < 4; nt++) {
                    mma_bf16(acc[mt][nt], ah[mt], bh[nt]);
                    mma_bf16(acc[mt][nt], al[mt], bh[nt]);
                    mma_bf16(acc[mt][nt], ah[mt], bl[nt]);
                }
        }
    };

    const int ntc = K >> 5;   // K/32 chunks
    loadG(0);
    storeS();
    __syncthreads();
    #pragma unroll 1
    for (int ch = 1; ch < ntc; ch++) {
        loadG(ch * 32);
        compute();
        __syncthreads();
        storeS();
        __syncthreads();
    }
    compute();

    // ---- epilogue: bias + act, direct stores (float2 per fragment row) ----
    #pragma unroll
    for (int nt = 0; nt < 4; nt++) {
        const int col = n0 + wn + nt * 8 + (lane & 3) * 2;
        const float2 bv = *reinterpret_cast<const float2*>(&bias[col]);
        #pragma unroll
        for (int mt = 0; mt < 4; mt++) {
            const int r0 = m0 + wm + mt * 16 + (lane >> 2);
            float u0 = acc[mt][nt][0] + bv.x;
            float u1 = acc[mt][nt][1] + bv.y;
            float u2 = acc[mt][nt][2] + bv.x;
            float u3 = acc[mt][nt][3] + bv.y;
            if (ACT == 1) {
                u0 = fmaxf(u0, 0.f); u1 = fmaxf(u1, 0.f);
                u2 = fmaxf(u2, 0.f); u3 = fmaxf(u3, 0.f);
            } else {
                u0 = tanhf(u0); u1 = tanhf(u1);
                u2 = tanhf(u2); u3 = tanhf(u3);
            }
            *reinterpret_cast<float2*>(&C[(size_t)r0 * N + col]) = make_float2(u0, u1);
            *reinterpret_cast<float2*>(&C[(size_t)(r0 + 8) * N + col]) = make_float2(u2, u3);
        }
    }
}

// ============================================================================
// weight split: W[K,N] f32 -> Wh/Wl [N,K] bf16 (transposed)
// ============================================================================
__global__ void wsplit_kernel(const float* __restrict__ W,
                              __nv_bfloat16* __restrict__ Wh,
                              __nv_bfloat16* __restrict__ Wl, int K, int N)
{
    int i = blockIdx.x * 256 + threadIdx.x;
    if (i >= K * N) return;
    int n = i / K, k = i - n * K;
    float w = W[(size_t)k * N + n];
    __nv_bfloat16 h = __float2bfloat16_rn(w);
    Wh[i] = h;
    Wl[i] = __float2bfloat16_rn(w - __bfloat162float(h));
}

// ============================================================================
// Scalar fp32 SGEMM (bitwise-exact sequential-k) — ENCODER ONLY.
// ============================================================================
template<int BM,int BN,int BK,int TM,int TN,int ACT>
__global__ __launch_bounds__((BM/TM)*(BN/TN), 2)
void gemm_bias_act(const float* __restrict__ A, const float* __restrict__ B,
                   const float* __restrict__ bias, float* __restrict__ C,
                   int M, int N, int K)
{
    constexpr int NT = (BM/TM)*(BN/TN);
    constexpr int LA = (BM*BK)/(NT*4);
    constexpr int LB = (BK*BN)/(NT*4);

    __shared__ __align__(16) float As[2][BK][BM];
    __shared__ __align__(16) float Bs[2][BK][BN];

    const int tid = threadIdx.x;
    const int m0 = blockIdx.x * BM;
    const int n0 = blockIdx.y * BN;
    const int tx = tid % (BN/TN);
    const int ty = tid / (BN/TN);

    float acc[TM][TN];
    #pragma unroll
    for (int i = 0; i < TM; i++)
        #pragma unroll
        for (int j = 0; j < TN; j++) acc[i][j] = 0.f;

    float4 ra[LA], rb[LB];

    #pragma unroll
    for (int j = 0; j < LA; j++) {
        int i = (tid + j*NT) * 4;
        int r = i / BK, c = i % BK;
        ra[j] = *reinterpret_cast<const float4*>(&A[(size_t)(m0 + r)*K + c]);
    }
    #pragma unroll
    for (int j = 0; j < LB; j++) {
        int i = (tid + j*NT) * 4;
        int r = i / BN, c = i % BN;
        rb[j] = *reinterpret_cast<const float4*>(&B[(size_t)r*N + n0 + c]);
    }
    #pragma unroll
    for (int j = 0; j < LA; j++) {
        int i = (tid + j*NT) * 4;
        int r = i / BK, c = i % BK;
        As[0][c+0][r] = ra[j].x; As[0][c+1][r] = ra[j].y;
        As[0][c+2][r] = ra[j].z; As[0][c+3][r] = ra[j].w;
    }
    #pragma unroll
    for (int j = 0; j < LB; j++) {
        int i = (tid + j*NT) * 4;
        int r = i / BN, c = i % BN;
        *reinterpret_cast<float4*>(&Bs[0][r][c]) = rb[j];
    }
    __syncthreads();

    const int ntiles = K / BK;
    #pragma unroll 1
    for (int t = 1; t < ntiles; t++) {
        const int k0 = t * BK;
        #pragma unroll
        for (int j = 0; j < LA; j++) {
            int i = (tid + j*NT) * 4;
            int r = i / BK, c = i % BK;
            ra[j] = *reinterpret_cast<const float4*>(&A[(size_t)(m0 + r)*K + k0 + c]);
        }
        #pragma unroll
        for (int j = 0; j < LB; j++) {
            int i = (tid + j*NT) * 4;
            int r = i / BN, c = i % BN;
            rb[j] = *reinterpret_cast<const float4*>(&B[(size_t)(k0 + r)*N + n0 + c]);
        }
        const int cur = (t - 1) & 1;
        #pragma unroll
        for (int k = 0; k < BK; k++) {
            float a[TM], b[TN];
            #pragma unroll
            for (int i = 0; i < TM; i += 4) {
                float4 v = *reinterpret_cast<const float4*>(&As[cur][k][ty*TM + i]);
                a[i] = v.x; a[i+1] = v.y; a[i+2] = v.z; a[i+3] = v.w;
            }
            #pragma unroll
            for (int j = 0; j < TN; j += 4) {
                float4 v = *reinterpret_cast<const float4*>(&Bs[cur][k][tx*TN + j]);
                b[j] = v.x; b[j+1] = v.y; b[j+2] = v.z; b[j+3] = v.w;
            }
            #pragma unroll
            for (int i = 0; i < TM; i++)
                #pragma unroll
                for (int j = 0; j < TN; j++)
                    acc[i][j] = fmaf(a[i], b[j], acc[i][j]);
        }
        const int nxt = t & 1;
        #pragma unroll
        for (int j = 0; j < LA; j++) {
            int i = (tid + j*NT) * 4;
            int r = i / BK, c = i % BK;
            As[nxt][c+0][r] = ra[j].x; As[nxt][c+1][r] = ra[j].y;
            As[nxt][c+2][r] = ra[j].z; As[nxt][c+3][r] = ra[j].w;
        }
        #pragma unroll
        for (int j = 0; j < LB; j++) {
            int i = (tid + j*NT) * 4;
            int r = i / BN, c = i % BN;
            *reinterpret_cast<float4*>(&Bs[nxt][r][c]) = rb[j];
        }
        __syncthreads();
    }
    {
        const int cur = (ntiles - 1) & 1;
        #pragma unroll
        for (int k = 0; k < BK; k++) {
            float a[TM], b[TN];
            #pragma unroll
            for (int i = 0; i < TM; i += 4) {
                float4 v = *reinterpret_cast<const float4*>(&As[cur][k][ty*TM + i]);
                a[i] = v.x; a[i+1] = v.y; a[i+2] = v.z; a[i+3] = v.w;
            }
            #pragma unroll
            for (int j = 0; j < TN; j += 4) {
                float4 v = *reinterpret_cast<const float4*>(&Bs[cur][k][tx*TN + j]);
                b[j] = v.x; b[j+1] = v.y; b[j+2] = v.z; b[j+3] = v.w;
            }
            #pragma unroll
            for (int i = 0; i < TM; i++)
                #pragma unroll
                for (int j = 0; j < TN; j++)
                    acc[i][j] = fmaf(a[i], b[j], acc[i][j]);
        }
    }

    float bv[TN];
    #pragma unroll
    for (int j = 0; j < TN; j++) bv[j] = bias[n0 + tx*TN + j];
    #pragma unroll
    for (int i = 0; i < TM; i++) {
        const int row = m0 + ty*TM + i;
        float* Cp = &C[(size_t)row*N + n0 + tx*TN];
        #pragma unroll
        for (int j = 0; j < TN; j += 4) {
            float vv[4];
            #pragma unroll
            for (int q = 0; q < 4; q++) {
                float u = acc[i][j+q] + bv[j+q];
                if (ACT == 1) u = fmaxf(u, 0.f);
                else if (ACT == 2) u = tanhf(u);
                vv[q] = u;
            }
            *reinterpret_cast<float4*>(&Cp[j]) = make_float4(vv[0], vv[1], vv[2], vv[3]);
        }
    }
}

// ============================================================================
// prep: codebook squared norms + zero the loss accumulator
// ============================================================================
__global__ void prep_kernel(const float* __restrict__ cb)
{
    const int c = blockIdx.x * blockDim.x + threadIdx.x;
    if (c == 0) g_loss = 0.0;
    if (c < NCODE) {
        const float* p = &cb[(size_t)c * LATD];
        float s = 0.f;
        #pragma unroll
        for (int i = 0; i < LATD; i++) s = fmaf(p[i], p[i], s);
        g_esq[c] = s;
    }
}

// ============================================================================
// VQ (bitwise-critical; reference rounding replicated) — UNCHANGED
// ============================================================================
__global__ __launch_bounds__(256)
void vq_kernel(const float* __restrict__ z, const float* __restrict__ cb,
               float* __restrict__ zq, float* __restrict__ idx_out)
{
    __shared__ __align__(16) float4 sc[128 * 16];
    __shared__ float sesq[128];
    __shared__ float wsum[8];

    const int tid = threadIdx.x;
    const int row = blockIdx.x * 256 + tid;

    float4 zr[16];
    const float4* zp = reinterpret_cast<const float4*>(&z[(size_t)row * LATD]);
    #pragma unroll
    for (int i = 0; i < 16; i++) zr[i] = zp[i];

    float z_sq = 0.f;
    #pragma unroll
    for (int i = 0; i < 16; i++) {
        z_sq = fmaf(zr[i].x, zr[i].x, z_sq);
        z_sq = fmaf(zr[i].y, zr[i].y, z_sq);
        z_sq = fmaf(zr[i].z, zr[i].z, z_sq);
        z_sq = fmaf(zr[i].w, zr[i].w, z_sq);
    }

    float best = 3.4028235e38f;
    int bi = 0;
    for (int c0 = 0; c0 < NCODE; c0 += 128) {
        __syncthreads();
        const float4* cp = reinterpret_cast<const float4*>(&cb[(size_t)c0 * LATD]);
        #pragma unroll
        for (int j = 0; j < 8; j++) sc[tid + j*256] = cp[tid + j*256];
        if (tid < 128) sesq[tid] = g_esq[c0 + tid];
        __syncthreads();

        #pragma unroll 4
        for (int c = 0; c < 128; c++) {
            const float4* e = &sc[c * 16];
            float acc = 0.f;
            #pragma unroll
            for (int i = 0; i < 16; i++) {
                float4 v = e[i];
                acc = fmaf(zr[i].x, v.x, acc);
                acc = fmaf(zr[i].y, v.y, acc);
                acc = fmaf(zr[i].z, v.z, acc);
                acc = fmaf(zr[i].w, v.w, acc);
            }
            float t = z_sq - 2.0f * acc;
            float d = t + sesq[c];
            if (d < best) { best = d; bi = c0 + c; }
        }
    }

    const float4* ep = reinterpret_cast<const float4*>(&cb[(size_t)bi * LATD]);
    float4* qp = reinterpret_cast<float4*>(&zq[(size_t)row * LATD]);
    float ls = 0.f;
    #pragma unroll
    for (int i = 0; i < 16; i++) {
        float4 e = ep[i];
        qp[i] = e;
        float dx = e.x - zr[i].x, dy = e.y - zr[i].y;
        float dz = e.z - zr[i].z, dw = e.w - zr[i].w;
        ls += dx*dx + dy*dy + dz*dz + dw*dw;
    }
    idx_out[row] = (float)bi;

    #pragma unroll
    for (int o = 16; o > 0; o >>= 1) ls += __shfl_down_sync(0xffffffffu, ls, o);
    if ((tid & 31) == 0) wsum[tid >> 5] = ls;
    __syncthreads();
    if (tid == 0) {
        float s = 0.f;
        #pragma unroll
        for (int i = 0; i < 8; i++) s += wsum[i];
        atomicAdd(&g_loss, (double)s);
    }
}

__global__ void fin_kernel(float* __restrict__ loss_out)
{
    loss_out[0] = (float)(COMMIT_BETA * g_loss / ((double)NROWS * LATD));
}

// ============================================================================
// launch
// ============================================================================
extern "C" void kernel_launch(void* const* d_in, const int* in_sizes, int n_in,
                              void* d_out, int out_size)
{
    const float* x   = (const float*)d_in[0];
    const float* We1 = (const float*)d_in[1];
    const float* be1 = (const float*)d_in[2];
    const float* We2 = (const float*)d_in[3];
    const float* be2 = (const float*)d_in[4];
    const float* We3 = (const float*)d_in[5];
    const float* be3 = (const float*)d_in[6];
    const float* cb  = (const float*)d_in[7];
    const float* Wd1 = (const float*)d_in[8];
    const float* bd1 = (const float*)d_in[9];
    const float* Wd2 = (const float*)d_in[10];
    const float* bd2 = (const float*)d_in[11];
    const float* Wd3 = (const float*)d_in[12];
    const float* bd3 = (const float*)d_in[13];

    float* out   = (float*)d_out;
    float* xrec  = out;
    float* zout  = out + (size_t)NROWS * IN_DIM;
    float* idxo  = zout + (size_t)NROWS * LATD;
    float* losso = idxo + NROWS;

    float *h1, *h2, *zq;
    cudaGetSymbolAddress((void**)&h1, g_h1);
    cudaGetSymbolAddress((void**)&h2, g_h2);
    cudaGetSymbolAddress((void**)&zq, g_zq);
    __nv_bfloat16 *w1h, *w1l, *w2h, *w2l, *w3h, *w3l;
    cudaGetSymbolAddress((void**)&w1h, g_w1h);
    cudaGetSymbolAddress((void**)&w1l, g_w1l);
    cudaGetSymbolAddress((void**)&w2h, g_w2h);
    cudaGetSymbolAddress((void**)&w2l, g_w2l);
    cudaGetSymbolAddress((void**)&w3h, g_w3h);
    cudaGetSymbolAddress((void**)&w3l, g_w3l);

    prep_kernel<<<4, 256>>>(cb);
    // split decoder weights (transposed) — independent of encoder
    wsplit_kernel<<<(LATD*H2D + 255)/256, 256>>>(Wd1, w1h, w1l, LATD, H2D);
    wsplit_kernel<<<(H2D*H1D + 255)/256, 256>>>(Wd2, w2h, w2l, H2D, H1D);
    wsplit_kernel<<<(H1D*IN_DIM + 255)/256, 256>>>(Wd3, w3h, w3l, H1D, IN_DIM);

    // encoder (bitwise-exact fp32)
    gemm_bias_act<128,128,8,8,8,1><<<dim3(NROWS/128, 4), 256>>>(x,  We1, be1, h1,   NROWS, 512,  1024);
    gemm_bias_act<128,128,8,8,8,1><<<dim3(NROWS/128, 2), 256>>>(h1, We2, be2, h2,   NROWS, 256,  512);
    gemm_bias_act<128, 64,16,8,4,0><<<dim3(NROWS/128, 1), 256>>>(h2, We3, be3, zout, NROWS, 64,   256);

    // vector quantization
    vq_kernel<<<NROWS/256, 256>>>(zout, cb, zq, idxo);

    // decoder on tensor cores (bf16 2-term split, fp32 accumulate)
    mma_gemm<1><<<dim3(H2D/128,   NROWS/128), 256>>>(zq, w1h, w1l, bd1, h2,   LATD, H2D);
    mma_gemm<1><<<dim3(H1D/128,   NROWS/128), 256>>>(h2, w2h, w2l, bd2, h1,   H2D,  H1D);
    mma_gemm<2><<<dim3(IN_DIM/128,NROWS/128), 256>>>(h1, w3h, w3l, bd3, xrec, H1D,  IN_DIM);

    fin_kernel<<<1, 1>>>(losso);
}